// round 10
// baseline (speedup 1.0000x reference)
#include <cuda_runtime.h>
#include <cuda_bf16.h>
#include <cuda_fp16.h>

#define HH   1024
#define WW   1024
#define RAD  40
#define EPSF 1e-3f
#define MAXIMG 12
#define HWSZ (HH * WW)
#define SEG  128         // rows per thread in vertical sliding passes
#define UNRV 8           // unroll in vertical passes
#define TPBV 64          // threads per block, vertical passes (1 col/thread)

#define TPBH 128         // threads per block, horizontal passes (8 px/thread)

#define PADL 40          // left padding (zeros) in csp
#define CSPN 1112        // PADL + 1024 + 48 right padding

// ---------------------------------------------------------------------------
// Scratch (static __device__ arrays -- no runtime allocation).
// Intermediates fp16 (inputs centered at 0 -> variance math insensitive to
// storage rounding).
// ---------------------------------------------------------------------------
__device__ uint2    g_V4h [MAXIMG * HWSZ];   // vert sums (I',p',I'p',I'I') 8B/px
__device__ unsigned g_abh [MAXIMG * HWSZ];   // (a,b) half2 4B/px
__device__ unsigned g_sabh[MAXIMG * HWSZ];   // vert sums (a,b) half2 4B/px

static __device__ __forceinline__ unsigned pack2(float a, float b)
{
    __half2 h = __floats2half2_rn(a, b);
    return *reinterpret_cast<unsigned*>(&h);
}
static __device__ __forceinline__ float2 unpack2(unsigned u)
{
    return __half22float2(*reinterpret_cast<__half2*>(&u));
}

// ---------------------------------------------------------------------------
// Stage 1 vertical: sliding column sums of (I', p', I'p', I'I'),  X' = X-0.5
// grid = (WW/TPBV, HH/SEG, nimg), block = TPBV
// ---------------------------------------------------------------------------
__global__ __launch_bounds__(TPBV)
void vpassA(const float* __restrict__ I, const float* __restrict__ P)
{
    int col = blockIdx.x * TPBV + threadIdx.x;
    int y0  = blockIdx.y * SEG;
    size_t base = (size_t)blockIdx.z * HWSZ + col;

    const float* __restrict__ Ic = I + base;
    const float* __restrict__ Pc = P + base;
    uint2* __restrict__ V = g_V4h + base;

    float sI = 0.f, sP = 0.f, sIP = 0.f, sII = 0.f;
    int ys = max(y0 - RAD, 0);
    int ye = min(y0 + RAD, HH - 1);
    for (int y = ys; y <= ye; y++) {
        float i = Ic[(size_t)y * WW] - 0.5f;
        float p = Pc[(size_t)y * WW] - 0.5f;
        sI += i; sP += p; sIP += i * p; sII += i * i;
    }

    for (int yb = y0; yb < y0 + SEG; yb += UNRV) {
        float ai[UNRV], ap[UNRV], si[UNRV], sp[UNRV];
#pragma unroll
        for (int u = 0; u < UNRV; u++) {
            int ya = yb + u + RAD + 1;
            int yu = yb + u - RAD;
            ai[u] = (ya < HH) ? Ic[(size_t)ya * WW] - 0.5f : 0.f;
            ap[u] = (ya < HH) ? Pc[(size_t)ya * WW] - 0.5f : 0.f;
            si[u] = (yu >= 0) ? Ic[(size_t)yu * WW] - 0.5f : 0.f;
            sp[u] = (yu >= 0) ? Pc[(size_t)yu * WW] - 0.5f : 0.f;
        }
#pragma unroll
        for (int u = 0; u < UNRV; u++) {
            int y = yb + u;
            uint2 uu;
            uu.x = pack2(sI, sP);
            uu.y = pack2(sIP, sII);
            V[(size_t)y * WW] = uu;
            sI  += ai[u] - si[u];
            sP  += ap[u] - sp[u];
            sIP += ai[u] * ap[u] - si[u] * sp[u];
            sII += ai[u] * ai[u] - si[u] * si[u];
        }
    }
}

// ---------------------------------------------------------------------------
// Stage 1 horizontal: row prefix-scan of V4h, 8 px/thread, 128 threads/row.
// Padded csp, conflict-free vectorized LDS; fused a/b -> abh.
// grid = (HH, nimg), block = TPBH
// ---------------------------------------------------------------------------
__global__ __launch_bounds__(TPBH)
void hpassA()
{
    __shared__ float csp[4][CSPN];
    __shared__ float wsum[4][4];

    int t    = threadIdx.x;
    int lane = t & 31;
    int warp = t >> 5;
    int row  = blockIdx.x;
    size_t base = ((size_t)blockIdx.y * HH + row) * WW;
    size_t off  = base + (size_t)t * 8;

    unsigned w[16];
    *(uint4*)(w + 0)  = *(const uint4*)(g_V4h + off);
    *(uint4*)(w + 4)  = *(const uint4*)(g_V4h + off + 2);
    *(uint4*)(w + 8)  = *(const uint4*)(g_V4h + off + 4);
    *(uint4*)(w + 12) = *(const uint4*)(g_V4h + off + 6);

    // e[q][j]: inclusive per-thread prefix sums (computed in place)
    float e[4][8];
#pragma unroll
    for (int j = 0; j < 8; j++) {
        float2 a = unpack2(w[2 * j]);
        float2 b = unpack2(w[2 * j + 1]);
        e[0][j] = a.x; e[1][j] = a.y; e[2][j] = b.x; e[3][j] = b.y;
    }
    float v[4];
#pragma unroll
    for (int q = 0; q < 4; q++) {
#pragma unroll
        for (int j = 1; j < 8; j++) e[q][j] += e[q][j - 1];
        v[q] = e[q][7];
    }

#pragma unroll
    for (int d = 1; d < 32; d <<= 1) {
#pragma unroll
        for (int q = 0; q < 4; q++) {
            float n = __shfl_up_sync(0xffffffffu, v[q], d);
            if (lane >= d) v[q] += n;
        }
    }
    if (lane == 31) {
#pragma unroll
        for (int q = 0; q < 4; q++) wsum[q][warp] = v[q];
    }
    __syncthreads();

    int x = t * 8;
#pragma unroll
    for (int q = 0; q < 4; q++) {
        float wb = 0.f;
#pragma unroll
        for (int w2 = 0; w2 < 3; w2++)
            wb += (w2 < warp) ? wsum[q][w2] : 0.f;
        float excl = wb + v[q] - e[q][7];
        *(float4*)&csp[q][PADL + x] =
            make_float4(excl, excl + e[q][0], excl + e[q][1], excl + e[q][2]);
        *(float4*)&csp[q][PADL + x + 4] =
            make_float4(excl + e[q][3], excl + e[q][4], excl + e[q][5], excl + e[q][6]);
        if (t < 10)
            *(float4*)&csp[q][t * 4] = make_float4(0.f, 0.f, 0.f, 0.f);
        if (t >= 112 && t < 124) {
            float tot = wsum[q][0] + wsum[q][1] + wsum[q][2] + wsum[q][3];
            *(float4*)&csp[q][PADL + WW + (t - 112) * 4] =
                make_float4(tot, tot, tot, tot);
        }
    }
    __syncthreads();

    float B[4][8];
#pragma unroll
    for (int q = 0; q < 4; q++) {
        float4 L0 = *(const float4*)&csp[q][PADL + x - RAD];       // x-40..x-37
        float4 L1 = *(const float4*)&csp[q][PADL + x - RAD + 4];   // x-36..x-33
        float4 HA = *(const float4*)&csp[q][PADL + x + RAD];       // x+40..x+43
        float4 HB = *(const float4*)&csp[q][PADL + x + RAD + 4];   // x+44..x+47
        float4 HC = *(const float4*)&csp[q][PADL + x + RAD + 8];   // x+48..x+51
        B[q][0] = HA.y - L0.x;
        B[q][1] = HA.z - L0.y;
        B[q][2] = HA.w - L0.z;
        B[q][3] = HB.x - L0.w;
        B[q][4] = HB.y - L1.x;
        B[q][5] = HB.z - L1.y;
        B[q][6] = HB.w - L1.z;
        B[q][7] = HC.x - L1.w;
    }

    float cy = (float)(min(row + RAD, HH - 1) - max(row - RAD, 0) + 1);

    unsigned ov[8];
#pragma unroll
    for (int k = 0; k < 8; k++) {
        float cx  = (float)(min(x + k + RAD, WW - 1) - max(x + k - RAD, 0) + 1);
        float inv = 1.0f / (cx * cy);

        float mIc = B[0][k] * inv;
        float mPc = B[1][k] * inv;
        float cov = B[2][k] * inv - mIc * mPc;
        float var = B[3][k] * inv - mIc * mIc;
        float a   = cov / (var + EPSF);
        float b   = (mPc + 0.5f) - a * (mIc + 0.5f);
        ov[k] = pack2(a, b);
    }
    *(uint4*)(g_abh + off)     = *(uint4*)(ov + 0);
    *(uint4*)(g_abh + off + 4) = *(uint4*)(ov + 4);
}

// ---------------------------------------------------------------------------
// Stage 2 vertical: sliding column sums of (a, b) from abh -> sabh.
// grid = (WW/TPBV, HH/SEG, nimg), block = TPBV
// ---------------------------------------------------------------------------
__global__ __launch_bounds__(TPBV)
void vpassB()
{
    int col = blockIdx.x * TPBV + threadIdx.x;
    int y0  = blockIdx.y * SEG;
    size_t base = (size_t)blockIdx.z * HWSZ + col;

    const unsigned* __restrict__ A = g_abh + base;
    unsigned*       __restrict__ S = g_sabh + base;

    float sa = 0.f, sb = 0.f;
    int ys = max(y0 - RAD, 0);
    int ye = min(y0 + RAD, HH - 1);
    for (int y = ys; y <= ye; y++) {
        float2 v = unpack2(A[(size_t)y * WW]);
        sa += v.x; sb += v.y;
    }

    for (int yb = y0; yb < y0 + SEG; yb += UNRV) {
        unsigned addr[UNRV], subr[UNRV];
#pragma unroll
        for (int u = 0; u < UNRV; u++) {
            int ya = yb + u + RAD + 1;
            int yu = yb + u - RAD;
            addr[u] = (ya < HH) ? A[(size_t)ya * WW] : 0u;
            subr[u] = (yu >= 0) ? A[(size_t)yu * WW] : 0u;
        }
#pragma unroll
        for (int u = 0; u < UNRV; u++) {
            int y = yb + u;
            S[(size_t)y * WW] = pack2(sa, sb);
            float2 av = unpack2(addr[u]);
            float2 sv = unpack2(subr[u]);
            sa += av.x - sv.x;
            sb += av.y - sv.y;
        }
    }
}

// ---------------------------------------------------------------------------
// Stage 2 horizontal: row scan of (sum_a, sum_b), 8 px/thread, padded csp,
// final output:  out = mean_a * I + mean_b
// grid = (HH, nimg), block = TPBH
// ---------------------------------------------------------------------------
__global__ __launch_bounds__(TPBH)
void hpassB(const float* __restrict__ I, float* __restrict__ out)
{
    __shared__ float csp[2][CSPN];
    __shared__ float wsum[2][4];

    int t    = threadIdx.x;
    int lane = t & 31;
    int warp = t >> 5;
    int row  = blockIdx.x;
    size_t base = ((size_t)blockIdx.y * HH + row) * WW;
    size_t off  = base + (size_t)t * 8;

    unsigned w[8];
    *(uint4*)(w + 0) = *(const uint4*)(g_sabh + off);
    *(uint4*)(w + 4) = *(const uint4*)(g_sabh + off + 4);

    float e[2][8];
#pragma unroll
    for (int j = 0; j < 8; j++) {
        float2 c = unpack2(w[j]);
        e[0][j] = c.x; e[1][j] = c.y;
    }
    float v[2];
#pragma unroll
    for (int q = 0; q < 2; q++) {
#pragma unroll
        for (int j = 1; j < 8; j++) e[q][j] += e[q][j - 1];
        v[q] = e[q][7];
    }

#pragma unroll
    for (int d = 1; d < 32; d <<= 1) {
#pragma unroll
        for (int q = 0; q < 2; q++) {
            float n = __shfl_up_sync(0xffffffffu, v[q], d);
            if (lane >= d) v[q] += n;
        }
    }
    if (lane == 31) {
#pragma unroll
        for (int q = 0; q < 2; q++) wsum[q][warp] = v[q];
    }
    __syncthreads();

    int x = t * 8;
#pragma unroll
    for (int q = 0; q < 2; q++) {
        float wb = 0.f;
#pragma unroll
        for (int w2 = 0; w2 < 3; w2++)
            wb += (w2 < warp) ? wsum[q][w2] : 0.f;
        float excl = wb + v[q] - e[q][7];
        *(float4*)&csp[q][PADL + x] =
            make_float4(excl, excl + e[q][0], excl + e[q][1], excl + e[q][2]);
        *(float4*)&csp[q][PADL + x + 4] =
            make_float4(excl + e[q][3], excl + e[q][4], excl + e[q][5], excl + e[q][6]);
        if (t < 10)
            *(float4*)&csp[q][t * 4] = make_float4(0.f, 0.f, 0.f, 0.f);
        if (t >= 112 && t < 124) {
            float tot = wsum[q][0] + wsum[q][1] + wsum[q][2] + wsum[q][3];
            *(float4*)&csp[q][PADL + WW + (t - 112) * 4] =
                make_float4(tot, tot, tot, tot);
        }
    }
    __syncthreads();

    float B[2][8];
#pragma unroll
    for (int q = 0; q < 2; q++) {
        float4 L0 = *(const float4*)&csp[q][PADL + x - RAD];
        float4 L1 = *(const float4*)&csp[q][PADL + x - RAD + 4];
        float4 HA = *(const float4*)&csp[q][PADL + x + RAD];
        float4 HB = *(const float4*)&csp[q][PADL + x + RAD + 4];
        float4 HC = *(const float4*)&csp[q][PADL + x + RAD + 8];
        B[q][0] = HA.y - L0.x;
        B[q][1] = HA.z - L0.y;
        B[q][2] = HA.w - L0.z;
        B[q][3] = HB.x - L0.w;
        B[q][4] = HB.y - L1.x;
        B[q][5] = HB.z - L1.y;
        B[q][6] = HB.w - L1.z;
        B[q][7] = HC.x - L1.w;
    }

    float cy = (float)(min(row + RAD, HH - 1) - max(row - RAD, 0) + 1);

    float iv[8];
    *(float4*)(iv + 0) = *(const float4*)(I + off);
    *(float4*)(iv + 4) = *(const float4*)(I + off + 4);

    float o[8];
#pragma unroll
    for (int k = 0; k < 8; k++) {
        float cx  = (float)(min(x + k + RAD, WW - 1) - max(x + k - RAD, 0) + 1);
        float inv = 1.0f / (cx * cy);
        o[k] = (B[0][k] * inv) * iv[k] + (B[1][k] * inv);
    }
    *(float4*)(out + off)     = *(float4*)(o + 0);
    *(float4*)(out + off + 4) = *(float4*)(o + 4);
}

// ---------------------------------------------------------------------------
extern "C" void kernel_launch(void* const* d_in, const int* in_sizes, int n_in,
                              void* d_out, int out_size)
{
    const float* I = (const float*)d_in[0];
    const float* P = (const float*)d_in[1];
    float* out     = (float*)d_out;

    int nimg = in_sizes[0] / HWSZ;      // B*C images of 1024x1024
    if (nimg > MAXIMG) nimg = MAXIMG;

    dim3 hgrid(HH, nimg);
    dim3 vgrid(WW / TPBV, HH / SEG, nimg);

    vpassA<<<vgrid, TPBV>>>(I, P);
    hpassA<<<hgrid, TPBH>>>();
    vpassB<<<vgrid, TPBV>>>();
    hpassB<<<hgrid, TPBH>>>(I, out);
}

// round 11
// speedup vs baseline: 1.0078x; 1.0078x over previous
#include <cuda_runtime.h>
#include <cuda_bf16.h>
#include <cuda_fp16.h>

#define HH   1024
#define WW   1024
#define RAD  40
#define EPSF 1e-3f
#define MAXIMG 12
#define HWSZ (HH * WW)
#define SEG  128         // rows per thread in vertical sliding passes
#define UNRV 8           // unroll in vertical passes
#define TPBV 64          // threads per block, vertical passes (1 col/thread)

#define PADL 40          // left padding (zeros) in csp
#define CSPN 1112        // PADL + 1024 + 48 right padding

// ---------------------------------------------------------------------------
// Scratch (static __device__ arrays -- no runtime allocation).
//   g_V4h : vertical box sums of (I',p',I'p',I'I') as 4x fp16  -- 8B/px
//   g_habh: HORIZONTAL box sums of (a,b) as half2              -- 4B/px
// ---------------------------------------------------------------------------
__device__ uint2    g_V4h [MAXIMG * HWSZ];
__device__ unsigned g_habh[MAXIMG * HWSZ];

static __device__ __forceinline__ unsigned pack2(float a, float b)
{
    __half2 h = __floats2half2_rn(a, b);
    return *reinterpret_cast<unsigned*>(&h);
}
static __device__ __forceinline__ float2 unpack2(unsigned u)
{
    return __half22float2(*reinterpret_cast<__half2*>(&u));
}

// ---------------------------------------------------------------------------
// Stage 1 vertical: sliding column sums of (I', p', I'p', I'I'),  X' = X-0.5
// grid = (WW/TPBV, HH/SEG, nimg), block = TPBV
// ---------------------------------------------------------------------------
__global__ __launch_bounds__(TPBV)
void vpassA(const float* __restrict__ I, const float* __restrict__ P)
{
    int col = blockIdx.x * TPBV + threadIdx.x;
    int y0  = blockIdx.y * SEG;
    size_t base = (size_t)blockIdx.z * HWSZ + col;

    const float* __restrict__ Ic = I + base;
    const float* __restrict__ Pc = P + base;
    uint2* __restrict__ V = g_V4h + base;

    float sI = 0.f, sP = 0.f, sIP = 0.f, sII = 0.f;
    int ys = max(y0 - RAD, 0);
    int ye = min(y0 + RAD, HH - 1);
#pragma unroll 4
    for (int y = ys; y <= ye; y++) {
        float i = Ic[(size_t)y * WW] - 0.5f;
        float p = Pc[(size_t)y * WW] - 0.5f;
        sI += i; sP += p; sIP += i * p; sII += i * i;
    }

    for (int yb = y0; yb < y0 + SEG; yb += UNRV) {
        float ai[UNRV], ap[UNRV], si[UNRV], sp[UNRV];
#pragma unroll
        for (int u = 0; u < UNRV; u++) {
            int ya = yb + u + RAD + 1;
            int yu = yb + u - RAD;
            ai[u] = (ya < HH) ? Ic[(size_t)ya * WW] - 0.5f : 0.f;
            ap[u] = (ya < HH) ? Pc[(size_t)ya * WW] - 0.5f : 0.f;
            si[u] = (yu >= 0) ? Ic[(size_t)yu * WW] - 0.5f : 0.f;
            sp[u] = (yu >= 0) ? Pc[(size_t)yu * WW] - 0.5f : 0.f;
        }
#pragma unroll
        for (int u = 0; u < UNRV; u++) {
            int y = yb + u;
            uint2 uu;
            uu.x = pack2(sI, sP);
            uu.y = pack2(sIP, sII);
            V[(size_t)y * WW] = uu;
            sI  += ai[u] - si[u];
            sP  += ap[u] - sp[u];
            sIP += ai[u] * ap[u] - si[u] * sp[u];
            sII += ai[u] * ai[u] - si[u] * si[u];
        }
    }
}

// ---------------------------------------------------------------------------
// Fused horizontal pass: phase 1 = row scan of V4h -> 2D box sums -> (a,b)
// in registers; phase 2 = row scan of (a,b) -> HORIZONTAL box sums -> g_habh.
// grid = (HH, nimg), block = 256 (4 px/thread, conflict-free LDS pattern)
// ---------------------------------------------------------------------------
__global__ __launch_bounds__(256)
void hpassAB()
{
    __shared__ float csp[4][CSPN];
    __shared__ float wsum[4][8];
    __shared__ float wsum2[2][8];

    int t    = threadIdx.x;
    int lane = t & 31;
    int warp = t >> 5;
    int row  = blockIdx.x;
    size_t base = ((size_t)blockIdx.y * HH + row) * WW;
    size_t off  = base + (size_t)t * 4;

    // ===================== phase 1: box means -> a,b =====================
    uint4 r0 = *(const uint4*)(g_V4h + off);
    uint4 r1 = *(const uint4*)(g_V4h + off + 2);

    float2 p0a = unpack2(r0.x), p0b = unpack2(r0.y);
    float2 p1a = unpack2(r0.z), p1b = unpack2(r0.w);
    float2 p2a = unpack2(r1.x), p2b = unpack2(r1.y);
    float2 p3a = unpack2(r1.z), p3b = unpack2(r1.w);

    float e[4][4] = {
        { p0a.x, p1a.x, p2a.x, p3a.x },   // sI'
        { p0a.y, p1a.y, p2a.y, p3a.y },   // sP'
        { p0b.x, p1b.x, p2b.x, p3b.x },   // sI'P'
        { p0b.y, p1b.y, p2b.y, p3b.y }    // sI'I'
    };

    float loc[4][4], v[4];
#pragma unroll
    for (int q = 0; q < 4; q++) {
        loc[q][0] = e[q][0];
        loc[q][1] = loc[q][0] + e[q][1];
        loc[q][2] = loc[q][1] + e[q][2];
        loc[q][3] = loc[q][2] + e[q][3];
        v[q] = loc[q][3];
    }
#pragma unroll
    for (int d = 1; d < 32; d <<= 1) {
#pragma unroll
        for (int q = 0; q < 4; q++) {
            float n = __shfl_up_sync(0xffffffffu, v[q], d);
            if (lane >= d) v[q] += n;
        }
    }
    if (lane == 31) {
#pragma unroll
        for (int q = 0; q < 4; q++) wsum[q][warp] = v[q];
    }
    __syncthreads();

    int x = t * 4;
#pragma unroll
    for (int q = 0; q < 4; q++) {
        float wb = 0.f;
#pragma unroll
        for (int w2 = 0; w2 < 7; w2++)
            wb += (w2 < warp) ? wsum[q][w2] : 0.f;
        float excl = wb + v[q] - loc[q][3];
        *(float4*)&csp[q][PADL + x] =
            make_float4(excl, excl + loc[q][0], excl + loc[q][1], excl + loc[q][2]);
        if (t < 10)
            *(float4*)&csp[q][t * 4] = make_float4(0.f, 0.f, 0.f, 0.f);
        if (t >= 240 && t < 252) {
            float tot = wsum[q][0] + wsum[q][1] + wsum[q][2] + wsum[q][3]
                      + wsum[q][4] + wsum[q][5] + wsum[q][6] + wsum[q][7];
            *(float4*)&csp[q][PADL + WW + (t - 240) * 4] =
                make_float4(tot, tot, tot, tot);
        }
    }
    __syncthreads();

    float cy = (float)(min(row + RAD, HH - 1) - max(row - RAD, 0) + 1);

    float B[4][4];
#pragma unroll
    for (int q = 0; q < 4; q++) {
        float4 L  = *(const float4*)&csp[q][PADL + x - RAD];
        float4 HA = *(const float4*)&csp[q][PADL + x + RAD];
        float4 HB = *(const float4*)&csp[q][PADL + x + RAD + 4];
        B[q][0] = HA.y - L.x;
        B[q][1] = HA.z - L.y;
        B[q][2] = HA.w - L.z;
        B[q][3] = HB.x - L.w;
    }

    float av[4], bv[4];
#pragma unroll
    for (int k = 0; k < 4; k++) {
        float cx  = (float)(min(x + k + RAD, WW - 1) - max(x + k - RAD, 0) + 1);
        float inv = 1.0f / (cx * cy);
        float mIc = B[0][k] * inv;
        float mPc = B[1][k] * inv;
        float cov = B[2][k] * inv - mIc * mPc;
        float var = B[3][k] * inv - mIc * mIc;
        float a   = cov / (var + EPSF);
        av[k] = a;
        bv[k] = (mPc + 0.5f) - a * (mIc + 0.5f);
    }

    // ===================== phase 2: horizontal box sums of (a,b) =========
    float loc2[2][4], v2[2];
    loc2[0][0] = av[0];
    loc2[0][1] = loc2[0][0] + av[1];
    loc2[0][2] = loc2[0][1] + av[2];
    loc2[0][3] = loc2[0][2] + av[3];
    loc2[1][0] = bv[0];
    loc2[1][1] = loc2[1][0] + bv[1];
    loc2[1][2] = loc2[1][1] + bv[2];
    loc2[1][3] = loc2[1][2] + bv[3];
    v2[0] = loc2[0][3];
    v2[1] = loc2[1][3];

#pragma unroll
    for (int d = 1; d < 32; d <<= 1) {
#pragma unroll
        for (int q = 0; q < 2; q++) {
            float n = __shfl_up_sync(0xffffffffu, v2[q], d);
            if (lane >= d) v2[q] += n;
        }
    }
    if (lane == 31) {
#pragma unroll
        for (int q = 0; q < 2; q++) wsum2[q][warp] = v2[q];
    }
    __syncthreads();   // also: all phase-1 csp reads complete before reuse

#pragma unroll
    for (int q = 0; q < 2; q++) {
        float wb = 0.f;
#pragma unroll
        for (int w2 = 0; w2 < 7; w2++)
            wb += (w2 < warp) ? wsum2[q][w2] : 0.f;
        float excl = wb + v2[q] - loc2[q][3];
        *(float4*)&csp[q][PADL + x] =
            make_float4(excl, excl + loc2[q][0], excl + loc2[q][1], excl + loc2[q][2]);
        // left pad [0..39] still zero from phase 1
        if (t >= 240 && t < 252) {
            float tot = wsum2[q][0] + wsum2[q][1] + wsum2[q][2] + wsum2[q][3]
                      + wsum2[q][4] + wsum2[q][5] + wsum2[q][6] + wsum2[q][7];
            *(float4*)&csp[q][PADL + WW + (t - 240) * 4] =
                make_float4(tot, tot, tot, tot);
        }
    }
    __syncthreads();

    float Bs[2][4];
#pragma unroll
    for (int q = 0; q < 2; q++) {
        float4 L  = *(const float4*)&csp[q][PADL + x - RAD];
        float4 HA = *(const float4*)&csp[q][PADL + x + RAD];
        float4 HB = *(const float4*)&csp[q][PADL + x + RAD + 4];
        Bs[q][0] = HA.y - L.x;
        Bs[q][1] = HA.z - L.y;
        Bs[q][2] = HA.w - L.z;
        Bs[q][3] = HB.x - L.w;
    }

    uint4 outv;
    unsigned* ov = &outv.x;
#pragma unroll
    for (int k = 0; k < 4; k++)
        ov[k] = pack2(Bs[0][k], Bs[1][k]);
    *(uint4*)(g_habh + off) = outv;
}

// ---------------------------------------------------------------------------
// Stage 2 vertical: sliding column sums of (hsum_a, hsum_b); fused output.
// out = (Sa/(cx*cy)) * I + Sb/(cx*cy)
// grid = (WW/TPBV, HH/SEG, nimg), block = TPBV
// ---------------------------------------------------------------------------
__global__ __launch_bounds__(TPBV)
void vpassC(const float* __restrict__ I, float* __restrict__ out)
{
    int col = blockIdx.x * TPBV + threadIdx.x;
    int y0  = blockIdx.y * SEG;
    size_t base = (size_t)blockIdx.z * HWSZ + col;

    const unsigned* __restrict__ Hc = g_habh + base;
    const float*    __restrict__ Ic = I + base;
    float*          __restrict__ Oc = out + base;

    float sa = 0.f, sb = 0.f;
    int ys = max(y0 - RAD, 0);
    int ye = min(y0 + RAD, HH - 1);
#pragma unroll 4
    for (int y = ys; y <= ye; y++) {
        float2 v = unpack2(Hc[(size_t)y * WW]);
        sa += v.x; sb += v.y;
    }

    float cx = (float)(min(col + RAD, WW - 1) - max(col - RAD, 0) + 1);

    for (int yb = y0; yb < y0 + SEG; yb += UNRV) {
        unsigned addr[UNRV], subr[UNRV];
        float iv[UNRV];
#pragma unroll
        for (int u = 0; u < UNRV; u++) {
            int ya = yb + u + RAD + 1;
            int yu = yb + u - RAD;
            addr[u] = (ya < HH) ? Hc[(size_t)ya * WW] : 0u;
            subr[u] = (yu >= 0) ? Hc[(size_t)yu * WW] : 0u;
            iv[u]   = Ic[(size_t)(yb + u) * WW];
        }
#pragma unroll
        for (int u = 0; u < UNRV; u++) {
            int y = yb + u;
            float cyv = (float)(min(y + RAD, HH - 1) - max(y - RAD, 0) + 1);
            float inv = 1.0f / (cx * cyv);
            Oc[(size_t)y * WW] = (sa * inv) * iv[u] + (sb * inv);
            float2 avp = unpack2(addr[u]);
            float2 svp = unpack2(subr[u]);
            sa += avp.x - svp.x;
            sb += avp.y - svp.y;
        }
    }
}

// ---------------------------------------------------------------------------
extern "C" void kernel_launch(void* const* d_in, const int* in_sizes, int n_in,
                              void* d_out, int out_size)
{
    const float* I = (const float*)d_in[0];
    const float* P = (const float*)d_in[1];
    float* out     = (float*)d_out;

    int nimg = in_sizes[0] / HWSZ;      // B*C images of 1024x1024
    if (nimg > MAXIMG) nimg = MAXIMG;

    dim3 hgrid(HH, nimg);
    dim3 vgrid(WW / TPBV, HH / SEG, nimg);

    vpassA<<<vgrid, TPBV>>>(I, P);
    hpassAB<<<hgrid, 256>>>();
    vpassC<<<vgrid, TPBV>>>(I, out);
}